// round 4
// baseline (speedup 1.0000x reference)
#include <cuda_runtime.h>
#include <cstdint>

// Problem constants
#define NROWS   8192      // 64*128
#define KDIM    512
#define NPCAS   128
#define NSTACKS 64
#define OUTDIM  8192

#define COEFF_F   3.7712361663282537f     // sqrt(128)/3 rounded to f32
#define TWO_PI_F  6.283185307179586f      // fl32(2*pi)

// GEMM scratch (static device global — no allocations allowed)
__device__ float g_xproj[NROWS * NPCAS];

// ---------------------------------------------------------------------------
// Kernel 1: x_ = x @ projector  (8192x512 @ 512x128).
// Sequential ascending-k, single accumulator, FMA per step — bit-matches the
// reference (confirmed: R2's mul+add variant was 5.5x worse).
// ---------------------------------------------------------------------------
__global__ __launch_bounds__(256, 2)
void gemm_kernel(const float* __restrict__ A, const float* __restrict__ B,
                 float* __restrict__ C)
{
    __shared__ float As[64 * 64];    // [row][k]  16KB
    __shared__ float Bs[64 * 128];   // [k][col]  32KB

    const int tid  = threadIdx.x;
    const int r0   = blockIdx.x * 64;
    const int warp = tid >> 5;
    const int lane = tid & 31;
    const int rbase = warp * 8;
    const int cb    = lane * 4;

    float acc[8][4];
#pragma unroll
    for (int i = 0; i < 8; i++)
#pragma unroll
        for (int j = 0; j < 4; j++) acc[i][j] = 0.0f;

    for (int kc = 0; kc < KDIM; kc += 64) {
        __syncthreads();
#pragma unroll
        for (int i = 0; i < 4; i++) {
            int idx = tid + i * 256;
            int row = idx >> 4;
            int k4  = idx & 15;
            ((float4*)As)[row * 16 + k4] =
                *(const float4*)(A + (size_t)(r0 + row) * KDIM + kc + k4 * 4);
        }
#pragma unroll
        for (int i = 0; i < 8; i++) {
            int idx = tid + i * 256;
            int kk  = idx >> 5;
            int c4  = idx & 31;
            ((float4*)Bs)[kk * 32 + c4] =
                *(const float4*)(B + (size_t)(kc + kk) * NPCAS + c4 * 4);
        }
        __syncthreads();

#pragma unroll 8
        for (int kk = 0; kk < 64; kk++) {
            float4 b4 = ((const float4*)Bs)[kk * 32 + lane];
#pragma unroll
            for (int i = 0; i < 8; i++) {
                float a = As[(rbase + i) * 64 + kk];
                acc[i][0] = fmaf(a, b4.x, acc[i][0]);
                acc[i][1] = fmaf(a, b4.y, acc[i][1]);
                acc[i][2] = fmaf(a, b4.z, acc[i][2]);
                acc[i][3] = fmaf(a, b4.w, acc[i][3]);
            }
        }
    }

#pragma unroll
    for (int i = 0; i < 8; i++) {
        float4 v = make_float4(acc[i][0], acc[i][1], acc[i][2], acc[i][3]);
        *(float4*)(C + (size_t)(r0 + rbase + i) * NPCAS + cb) = v;
    }
}

// ---------------------------------------------------------------------------
// Accurate fast cos: Cody-Waite pi/2 reduction (FMA-exact) + cephes polys.
// ---------------------------------------------------------------------------
__device__ __forceinline__ float fast_cos(float x)
{
    float t  = fmaf(x, 0.6366197723675814f, 12582912.0f);   // 1.5*2^23
    int   qi = __float_as_int(t);
    float q  = t - 12582912.0f;
    float r = fmaf(q, -1.5707963705062866f, x);
    r = fmaf(q, 4.3711388286737929e-8f, r);

    float s = r * r;
    float pc = fmaf(s, 2.443315711809948e-5f, -1.388731625493765e-3f);
    pc = fmaf(s, pc, 4.166664568298827e-2f);
    pc = fmaf(s, pc, -0.5f);
    pc = fmaf(s, pc, 1.0f);
    float ps = fmaf(s, -1.9515295891e-4f, 8.3321608736e-3f);
    ps = fmaf(s, ps, -1.6666654611e-1f);
    ps = fmaf(ps, s * r, r);

    float res = (qi & 1) ? ps : pc;
    unsigned sgn = ((unsigned)(qi + 1) & 2u) << 30;
    return __int_as_float(__float_as_int(res) ^ sgn);
}

__device__ __forceinline__ float xor_sign(float f, unsigned m)
{
    return __int_as_float(__float_as_int(f) ^ (int)m);
}

// One 128-pt FWHT across a warp, 4 consecutive elements per lane.
// Exact reference stage order h=1,2,4,...,64.
// Does NOT apply the COEFF scale — callers handle it.
__device__ __forceinline__ void fwht_core(float& f0, float& f1, float& f2, float& f3,
                                          unsigned m0, unsigned m1, unsigned m2, unsigned m3,
                                          int lane)
{
    // sign flip (d * y, exact)
    f0 = xor_sign(f0, m0); f1 = xor_sign(f1, m1);
    f2 = xor_sign(f2, m2); f3 = xor_sign(f3, m3);
    // h = 1
    float t0 = f0 + f1, t1 = f0 - f1, t2 = f2 + f3, t3 = f2 - f3;
    // h = 2
    f0 = t0 + t2; f1 = t1 + t3; f2 = t0 - t2; f3 = t1 - t3;
    // h = 4..64
#pragma unroll
    for (int L = 1; L <= 16; L <<= 1) {
        unsigned sm = (lane & L) ? 0x80000000u : 0u;
        float p0 = __shfl_xor_sync(0xffffffffu, f0, L);
        float p1 = __shfl_xor_sync(0xffffffffu, f1, L);
        float p2 = __shfl_xor_sync(0xffffffffu, f2, L);
        float p3 = __shfl_xor_sync(0xffffffffu, f3, L);
        f0 = p0 + xor_sign(f0, sm);
        f1 = p1 + xor_sign(f1, sm);
        f2 = p2 + xor_sign(f2, sm);
        f3 = p3 + xor_sign(f3, sm);
    }
}

// ---------------------------------------------------------------------------
// Kernel 2. Final step must be SEPARATE mul then add (two roundings) to match
// the reference: __fmul_rn / __fadd_rn intrinsics are never contracted by
// nvcc (evidence: the contracted-FFMA version differs by exactly one
// last-step rounding, rel_err 1.04e-3, bit-identical across R1/R3).
// ---------------------------------------------------------------------------
__global__ __launch_bounds__(512, 2)
void fwht_cos_kernel(const float* __restrict__ xp, const float* __restrict__ d,
                     const float* __restrict__ b, float* __restrict__ out)
{
    __shared__ float xs[16 * 128];

    const int tid     = threadIdx.x;
    const int rowBase = blockIdx.x * 16;

    ((float4*)xs)[tid] = *(const float4*)(xp + (size_t)rowBase * NPCAS + tid * 4);
    __syncthreads();

    const int warp = tid >> 5;
    const int lane = tid & 31;
    const int e    = lane * 4;

#pragma unroll
    for (int si = 0; si < 4; si++) {
        const int s = warp * 4 + si;
        uint4 d0 = *(const uint4*)(d + (size_t)s * NPCAS + e);
        uint4 d1 = *(const uint4*)(d + (size_t)(NSTACKS + s) * NPCAS + e);
        unsigned m00 = d0.x & 0x80000000u, m01 = d0.y & 0x80000000u;
        unsigned m02 = d0.z & 0x80000000u, m03 = d0.w & 0x80000000u;
        unsigned m10 = d1.x & 0x80000000u, m11 = d1.y & 0x80000000u;
        unsigned m12 = d1.z & 0x80000000u, m13 = d1.w & 0x80000000u;
        float4 bv = *(const float4*)(b + (size_t)s * NPCAS + e);
        float bb0 = __fmul_rn(bv.x, TWO_PI_F), bb1 = __fmul_rn(bv.y, TWO_PI_F);
        float bb2 = __fmul_rn(bv.z, TWO_PI_F), bb3 = __fmul_rn(bv.w, TWO_PI_F);

        for (int r = 0; r < 16; r++) {
            float4 xv = *(const float4*)&xs[r * 128 + e];
            float f0 = xv.x, f1 = xv.y, f2 = xv.z, f3 = xv.w;

            // transform 0: explicit COEFF multiply (separate rounding)
            fwht_core(f0, f1, f2, f3, m00, m01, m02, m03, lane);
            f0 = __fmul_rn(f0, COEFF_F); f1 = __fmul_rn(f1, COEFF_F);
            f2 = __fmul_rn(f2, COEFF_F); f3 = __fmul_rn(f3, COEFF_F);

            // transform 1, then SEPARATE COEFF mul and bias add (no FMA!)
            fwht_core(f0, f1, f2, f3, m10, m11, m12, m13, lane);

            float4 o;
            o.x = fast_cos(__fadd_rn(__fmul_rn(f0, COEFF_F), bb0));
            o.y = fast_cos(__fadd_rn(__fmul_rn(f1, COEFF_F), bb1));
            o.z = fast_cos(__fadd_rn(__fmul_rn(f2, COEFF_F), bb2));
            o.w = fast_cos(__fadd_rn(__fmul_rn(f3, COEFF_F), bb3));

            *(float4*)(out + (size_t)(rowBase + r) * OUTDIM + s * NPCAS + e) = o;
        }
    }
}

// ---------------------------------------------------------------------------
extern "C" void kernel_launch(void* const* d_in, const int* in_sizes, int n_in,
                              void* d_out, int out_size)
{
    const float* x    = (const float*)d_in[0];   // (64,128,512)
    const float* proj = (const float*)d_in[1];   // (512,128)
    const float* d    = (const float*)d_in[2];   // (2,64,128)
    const float* b    = (const float*)d_in[3];   // (8192,)
    float* out        = (float*)d_out;           // (64,128,8192)

    float* xproj;
    cudaGetSymbolAddress((void**)&xproj, g_xproj);

    gemm_kernel<<<NROWS / 64, 256>>>(x, proj, xproj);
    fwht_cos_kernel<<<NROWS / 16, 512>>>(xproj, d, b, out);
}

// round 8
// speedup vs baseline: 1.0668x; 1.0668x over previous
#include <cuda_runtime.h>
#include <cstdint>

#define NROWS   8192
#define KDIM    512
#define NPCAS   128
#define NSTACKS 64
#define OUTDIM  8192

#define COEFF_F   3.7712361663282537f
#define TWO_PI_F  6.283185307179586f

__device__ float g_xproj[NROWS * NPCAS];

// ---------------------------------------------------------------------------
// Kernel 1: unchanged (bit-matches reference; sequential-k FMA).
// ---------------------------------------------------------------------------
__global__ __launch_bounds__(256, 2)
void gemm_kernel(const float* __restrict__ A, const float* __restrict__ B,
                 float* __restrict__ C)
{
    __shared__ float As[64 * 64];
    __shared__ float Bs[64 * 128];

    const int tid  = threadIdx.x;
    const int r0   = blockIdx.x * 64;
    const int warp = tid >> 5;
    const int lane = tid & 31;
    const int rbase = warp * 8;
    const int cb    = lane * 4;

    float acc[8][4];
#pragma unroll
    for (int i = 0; i < 8; i++)
#pragma unroll
        for (int j = 0; j < 4; j++) acc[i][j] = 0.0f;

    for (int kc = 0; kc < KDIM; kc += 64) {
        __syncthreads();
#pragma unroll
        for (int i = 0; i < 4; i++) {
            int idx = tid + i * 256;
            int row = idx >> 4;
            int k4  = idx & 15;
            ((float4*)As)[row * 16 + k4] =
                *(const float4*)(A + (size_t)(r0 + row) * KDIM + kc + k4 * 4);
        }
#pragma unroll
        for (int i = 0; i < 8; i++) {
            int idx = tid + i * 256;
            int kk  = idx >> 5;
            int c4  = idx & 31;
            ((float4*)Bs)[kk * 32 + c4] =
                *(const float4*)(B + (size_t)(kc + kk) * NPCAS + c4 * 4);
        }
        __syncthreads();

#pragma unroll 8
        for (int kk = 0; kk < 64; kk++) {
            float4 b4 = ((const float4*)Bs)[kk * 32 + lane];
#pragma unroll
            for (int i = 0; i < 8; i++) {
                float a = As[(rbase + i) * 64 + kk];
                acc[i][0] = fmaf(a, b4.x, acc[i][0]);
                acc[i][1] = fmaf(a, b4.y, acc[i][1]);
                acc[i][2] = fmaf(a, b4.z, acc[i][2]);
                acc[i][3] = fmaf(a, b4.w, acc[i][3]);
            }
        }
    }

#pragma unroll
    for (int i = 0; i < 8; i++) {
        float4 v = make_float4(acc[i][0], acc[i][1], acc[i][2], acc[i][3]);
        *(float4*)(C + (size_t)(r0 + rbase + i) * NPCAS + cb) = v;
    }
}

// ---------------------------------------------------------------------------
// Packed f32x2 helpers. WARNING (R7 lesson): ptxas fuses a packed
// mul.rn.f32x2 whose result feeds add.rn.f32x2 into fma.rn.f32x2 — never use
// the packed pair where two separate roundings are semantically required.
// ---------------------------------------------------------------------------
typedef unsigned long long u64t;

__device__ __forceinline__ u64t pack2(float lo, float hi) {
    u64t r; asm("mov.b64 %0, {%1, %2};" : "=l"(r) : "f"(lo), "f"(hi)); return r;
}
__device__ __forceinline__ void unpack2(u64t v, float& lo, float& hi) {
    asm("mov.b64 {%0, %1}, %2;" : "=f"(lo), "=f"(hi) : "l"(v));
}
__device__ __forceinline__ u64t fma2(u64t a, u64t b, u64t c) {
    u64t r; asm("fma.rn.f32x2 %0, %1, %2, %3;" : "=l"(r) : "l"(a), "l"(b), "l"(c)); return r;
}
__device__ __forceinline__ u64t mul2(u64t a, u64t b) {
    u64t r; asm("mul.rn.f32x2 %0, %1, %2;" : "=l"(r) : "l"(a), "l"(b)); return r;
}

// Packed cos for a pair of already-biased arguments X = (x0, x1).
// Pure fma chains + muls feeding non-add consumers — no fusion hazard.
// Per-half arithmetic identical to R4's scalar fast_cos.
__device__ __forceinline__ void fast_cos2(u64t X, float& o0, float& o1)
{
    const u64t INV2   = pack2(0.6366197723675814f, 0.6366197723675814f);
    const u64t MAG2   = pack2(12582912.0f, 12582912.0f);
    const u64t NMAG2  = pack2(-12582912.0f, -12582912.0f);
    const u64t NPIH2  = pack2(-1.5707963705062866f, -1.5707963705062866f);
    const u64t PIL2   = pack2(4.3711388286737929e-8f, 4.3711388286737929e-8f);
    const u64t CC3    = pack2(2.443315711809948e-5f, 2.443315711809948e-5f);
    const u64t CC2    = pack2(-1.388731625493765e-3f, -1.388731625493765e-3f);
    const u64t CC1    = pack2(4.166664568298827e-2f, 4.166664568298827e-2f);
    const u64t CHALF  = pack2(-0.5f, -0.5f);
    const u64t CONE   = pack2(1.0f, 1.0f);
    const u64t SS3    = pack2(-1.9515295891e-4f, -1.9515295891e-4f);
    const u64t SS2    = pack2(8.3321608736e-3f, 8.3321608736e-3f);
    const u64t SS1    = pack2(-1.6666654611e-1f, -1.6666654611e-1f);
    const u64t ONE2   = pack2(1.0f, 1.0f);

    u64t T = fma2(X, INV2, MAG2);
    float tlo, thi; unpack2(T, tlo, thi);
    int q0 = __float_as_int(tlo);
    int q1 = __float_as_int(thi);
    // Q = T - 12582912 computed as fma(T, 1, -MAG): single rounding, and the
    // subtraction is exact anyway (Sterbenz) -> identical to scalar path.
    u64t Q = fma2(T, ONE2, NMAG2);
    u64t R = fma2(Q, NPIH2, X);
    R = fma2(Q, PIL2, R);
    u64t S = mul2(R, R);                 // feeds fma2 only — safe

    u64t PC = fma2(S, CC3, CC2);
    PC = fma2(S, PC, CC1);
    PC = fma2(S, PC, CHALF);
    PC = fma2(S, PC, CONE);

    u64t PS = fma2(S, SS3, SS2);
    PS = fma2(S, PS, SS1);
    u64t SR = mul2(S, R);                // feeds fma2 as multiplicand — safe
    PS = fma2(PS, SR, R);

    float pc0, pc1, ps0, ps1;
    unpack2(PC, pc0, pc1);
    unpack2(PS, ps0, ps1);

    float v0 = (q0 & 1) ? ps0 : pc0;
    float v1 = (q1 & 1) ? ps1 : pc1;
    o0 = __int_as_float(__float_as_int(v0) ^ (int)(((unsigned)(q0 + 1) & 2u) << 30));
    o1 = __int_as_float(__float_as_int(v1) ^ (int)(((unsigned)(q1 + 1) & 2u) << 30));
}

__device__ __forceinline__ float xor_signw(float f, unsigned w)
{
    return __int_as_float(__float_as_int(f) ^ ((int)w & 0x80000000));
}

// 128-pt FWHT across warp, 4 elems/lane. Cross-lane stages use fmaf(±1,f,p)
// (rounds identically to ±f + p).
__device__ __forceinline__ void fwht_core(float& f0, float& f1, float& f2, float& f3,
                                          unsigned d0, unsigned d1, unsigned d2, unsigned d3,
                                          const float sg1, const float sg2, const float sg4,
                                          const float sg8, const float sg16)
{
    f0 = xor_signw(f0, d0); f1 = xor_signw(f1, d1);
    f2 = xor_signw(f2, d2); f3 = xor_signw(f3, d3);
    float t0 = f0 + f1, t1 = f0 - f1, t2 = f2 + f3, t3 = f2 - f3;
    f0 = t0 + t2; f1 = t1 + t3; f2 = t0 - t2; f3 = t1 - t3;
    {
        float p0 = __shfl_xor_sync(0xffffffffu, f0, 1);
        float p1 = __shfl_xor_sync(0xffffffffu, f1, 1);
        float p2 = __shfl_xor_sync(0xffffffffu, f2, 1);
        float p3 = __shfl_xor_sync(0xffffffffu, f3, 1);
        f0 = fmaf(sg1, f0, p0); f1 = fmaf(sg1, f1, p1);
        f2 = fmaf(sg1, f2, p2); f3 = fmaf(sg1, f3, p3);
    }
    {
        float p0 = __shfl_xor_sync(0xffffffffu, f0, 2);
        float p1 = __shfl_xor_sync(0xffffffffu, f1, 2);
        float p2 = __shfl_xor_sync(0xffffffffu, f2, 2);
        float p3 = __shfl_xor_sync(0xffffffffu, f3, 2);
        f0 = fmaf(sg2, f0, p0); f1 = fmaf(sg2, f1, p1);
        f2 = fmaf(sg2, f2, p2); f3 = fmaf(sg2, f3, p3);
    }
    {
        float p0 = __shfl_xor_sync(0xffffffffu, f0, 4);
        float p1 = __shfl_xor_sync(0xffffffffu, f1, 4);
        float p2 = __shfl_xor_sync(0xffffffffu, f2, 4);
        float p3 = __shfl_xor_sync(0xffffffffu, f3, 4);
        f0 = fmaf(sg4, f0, p0); f1 = fmaf(sg4, f1, p1);
        f2 = fmaf(sg4, f2, p2); f3 = fmaf(sg4, f3, p3);
    }
    {
        float p0 = __shfl_xor_sync(0xffffffffu, f0, 8);
        float p1 = __shfl_xor_sync(0xffffffffu, f1, 8);
        float p2 = __shfl_xor_sync(0xffffffffu, f2, 8);
        float p3 = __shfl_xor_sync(0xffffffffu, f3, 8);
        f0 = fmaf(sg8, f0, p0); f1 = fmaf(sg8, f1, p1);
        f2 = fmaf(sg8, f2, p2); f3 = fmaf(sg8, f3, p3);
    }
    {
        float p0 = __shfl_xor_sync(0xffffffffu, f0, 16);
        float p1 = __shfl_xor_sync(0xffffffffu, f1, 16);
        float p2 = __shfl_xor_sync(0xffffffffu, f2, 16);
        float p3 = __shfl_xor_sync(0xffffffffu, f3, 16);
        f0 = fmaf(sg16, f0, p0); f1 = fmaf(sg16, f1, p1);
        f2 = fmaf(sg16, f2, p2); f3 = fmaf(sg16, f3, p3);
    }
}

// ---------------------------------------------------------------------------
// Kernel 2: warp-item grid-stride. Item = (row, stack-octet).
// Final scale+bias: SCALAR __fmul_rn / __fadd_rn (proven never contracted).
// ---------------------------------------------------------------------------
#define K2_BLOCKS  444          // 148 * 3
#define K2_THREADS 256
#define K2_NW      (K2_BLOCKS * K2_THREADS / 32)
#define NITEMS     (NROWS * 8)

__global__ __launch_bounds__(K2_THREADS)
void fwht_cos_kernel(const float* __restrict__ xp, const float* __restrict__ d,
                     const float* __restrict__ b, float* __restrict__ out)
{
    const int lane = threadIdx.x & 31;
    const int gw   = (blockIdx.x * K2_THREADS + threadIdx.x) >> 5;
    const int e    = lane * 4;

    const float sg1  = (lane & 1)  ? -1.0f : 1.0f;
    const float sg2  = (lane & 2)  ? -1.0f : 1.0f;
    const float sg4  = (lane & 4)  ? -1.0f : 1.0f;
    const float sg8  = (lane & 8)  ? -1.0f : 1.0f;
    const float sg16 = (lane & 16) ? -1.0f : 1.0f;

    for (int item = gw; item < NITEMS; item += K2_NW) {
        const int r = item >> 3;
        const int o = item & 7;

        float4 xv = *(const float4*)(xp + (size_t)r * NPCAS + e);
        float* orow = out + (size_t)r * OUTDIM;

#pragma unroll
        for (int si = 0; si < 8; si++) {
            const int s = o * 8 + si;
            uint4 dw0 = *(const uint4*)(d + (size_t)s * NPCAS + e);
            uint4 dw1 = *(const uint4*)(d + (size_t)(NSTACKS + s) * NPCAS + e);
            float4 bv = *(const float4*)(b + (size_t)s * NPCAS + e);
            float bb0 = __fmul_rn(bv.x, TWO_PI_F), bb1 = __fmul_rn(bv.y, TWO_PI_F);
            float bb2 = __fmul_rn(bv.z, TWO_PI_F), bb3 = __fmul_rn(bv.w, TWO_PI_F);

            float f0 = xv.x, f1 = xv.y, f2 = xv.z, f3 = xv.w;

            fwht_core(f0, f1, f2, f3, dw0.x, dw0.y, dw0.z, dw0.w,
                      sg1, sg2, sg4, sg8, sg16);
            f0 = __fmul_rn(f0, COEFF_F); f1 = __fmul_rn(f1, COEFF_F);
            f2 = __fmul_rn(f2, COEFF_F); f3 = __fmul_rn(f3, COEFF_F);

            fwht_core(f0, f1, f2, f3, dw1.x, dw1.y, dw1.z, dw1.w,
                      sg1, sg2, sg4, sg8, sg16);

            // SEPARATE scalar mul then add (two roundings) — matches reference
            float a0 = __fadd_rn(__fmul_rn(f0, COEFF_F), bb0);
            float a1 = __fadd_rn(__fmul_rn(f1, COEFF_F), bb1);
            float a2 = __fadd_rn(__fmul_rn(f2, COEFF_F), bb2);
            float a3 = __fadd_rn(__fmul_rn(f3, COEFF_F), bb3);

            float4 ov;
            fast_cos2(pack2(a0, a1), ov.x, ov.y);
            fast_cos2(pack2(a2, a3), ov.z, ov.w);

            *(float4*)(orow + s * NPCAS + e) = ov;
        }
    }
}

// ---------------------------------------------------------------------------
extern "C" void kernel_launch(void* const* d_in, const int* in_sizes, int n_in,
                              void* d_out, int out_size)
{
    const float* x    = (const float*)d_in[0];
    const float* proj = (const float*)d_in[1];
    const float* d    = (const float*)d_in[2];
    const float* b    = (const float*)d_in[3];
    float* out        = (float*)d_out;

    float* xproj;
    cudaGetSymbolAddress((void**)&xproj, g_xproj);

    gemm_kernel<<<NROWS / 64, 256>>>(x, proj, xproj);
    fwht_cos_kernel<<<K2_BLOCKS, K2_THREADS>>>(xproj, d, b, out);
}